// round 1
// baseline (speedup 1.0000x reference)
#include <cuda_runtime.h>
#include <cuda_bf16.h>
#include <cstddef>

// Problem constants
#define BATCH 4
#define SEQ   2048
#define DIM   1024
#define HEADS 16
#define DHEAD 64
#define INNER (HEADS*DHEAD)      // 1024
#define M_ROWS (BATCH*SEQ)       // 8192
#define SCALE 0.125f             // 64^-0.5

// Scratch (no allocations allowed -> __device__ globals)
__device__ float g_qkv[(size_t)3*BATCH*HEADS*SEQ*DHEAD];   // [which][b][h][n][d] ~100MB
__device__ float g_attn[(size_t)BATCH*SEQ*INNER];          // [b][n][h*64+d]     ~33MB

// ---------------------------------------------------------------------------
// Tiled fp32 GEMM: C[M,N] = A[M,K] @ B[K,N]
// MODE 0: A = x, scatter epilogue into g_qkv
// MODE 1: A = g_attn, epilogue writes Cout + bias
// ---------------------------------------------------------------------------
#define BM 128
#define BN 128
#define BKK 16
#define TM 8
#define TN 8

template<int MODE>
__global__ __launch_bounds__(256) void gemm_kernel(const float* __restrict__ A,
                                                   const float* __restrict__ Bw,
                                                   const float* __restrict__ bias,
                                                   float* __restrict__ Cout,
                                                   int M, int N, int K)
{
    __shared__ float As[BKK][BM];
    __shared__ float Bs[BKK][BN];

    const int tid = threadIdx.x;
    const int tx = tid & 15;        // 0..15 -> col group
    const int ty = tid >> 4;        // 0..15 -> row group
    const int rowBase = blockIdx.y * BM;
    const int colBase = blockIdx.x * BN;

    const float* Ap = (MODE == 0) ? A : g_attn;

    float acc[TM][TN];
    #pragma unroll
    for (int i = 0; i < TM; i++)
        #pragma unroll
        for (int j = 0; j < TN; j++) acc[i][j] = 0.f;

    for (int k0 = 0; k0 < K; k0 += BKK) {
        // Load A tile 128x16 (512 float4, 2 per thread), store transposed
        #pragma unroll
        for (int i = 0; i < 2; i++) {
            int f  = tid * 2 + i;           // 0..511
            int ar = f >> 2;                // 0..127
            int ac = (f & 3) * 4;           // 0,4,8,12
            float4 v = *(const float4*)(Ap + (size_t)(rowBase + ar) * K + k0 + ac);
            As[ac + 0][ar] = v.x;
            As[ac + 1][ar] = v.y;
            As[ac + 2][ar] = v.z;
            As[ac + 3][ar] = v.w;
        }
        // Load B tile 16x128 (512 float4, 2 per thread)
        #pragma unroll
        for (int i = 0; i < 2; i++) {
            int f  = tid * 2 + i;
            int br = f >> 5;                // 0..15
            int bc = (f & 31) * 4;          // 0..124
            *(float4*)(&Bs[br][bc]) =
                *(const float4*)(Bw + (size_t)(k0 + br) * N + colBase + bc);
        }
        __syncthreads();

        #pragma unroll
        for (int k = 0; k < BKK; k++) {
            float4 a0 = *(const float4*)(&As[k][ty * TM]);
            float4 a1 = *(const float4*)(&As[k][ty * TM + 4]);
            float4 b0 = *(const float4*)(&Bs[k][tx * TN]);
            float4 b1 = *(const float4*)(&Bs[k][tx * TN + 4]);
            float a[TM] = {a0.x, a0.y, a0.z, a0.w, a1.x, a1.y, a1.z, a1.w};
            float b[TN] = {b0.x, b0.y, b0.z, b0.w, b1.x, b1.y, b1.z, b1.w};
            #pragma unroll
            for (int i = 0; i < TM; i++)
                #pragma unroll
                for (int j = 0; j < TN; j++)
                    acc[i][j] += a[i] * b[j];
        }
        __syncthreads();
    }

    // Epilogue
    #pragma unroll
    for (int i = 0; i < TM; i++) {
        int r = rowBase + ty * TM + i;
        #pragma unroll
        for (int j = 0; j < TN; j++) {
            int c = colBase + tx * TN + j;
            if (MODE == 0) {
                // scatter into g_qkv[which][b][h][n][d]
                int b   = r >> 11;          // /2048
                int n   = r & 2047;
                int wch = c >> 10;          // /1024
                int rem = c & 1023;
                int h   = rem >> 6;
                int d   = rem & 63;
                g_qkv[((((size_t)wch * BATCH + b) * HEADS + h) * SEQ + n) * DHEAD + d] = acc[i][j];
            } else {
                Cout[(size_t)r * N + c] = acc[i][j] + bias[c];
            }
        }
    }
}

// ---------------------------------------------------------------------------
// Causal flash attention (fp32). Grid: (32 qblocks, 64 bh). Block: 256.
// 64 query rows x 32 key tile. 4 threads per query row.
// ---------------------------------------------------------------------------
__global__ __launch_bounds__(256) void attn_kernel()
{
    __shared__ float Qs[64][65];
    __shared__ float Ks[32][65];
    __shared__ float Vs[32][64];
    __shared__ float Ss[64][33];

    const int qb  = gridDim.x - 1 - blockIdx.x;   // big-work blocks first
    const int bh  = blockIdx.y;
    const int b   = bh >> 4;
    const int h   = bh & 15;
    const int tid = threadIdx.x;
    const int r   = tid >> 2;      // query row within tile (0..63)
    const int cg  = tid & 3;       // column group within row (0..3)
    const int qi  = qb * 64 + r;   // global query index

    const float* Qbase = g_qkv + ((((size_t)0 * BATCH + b) * HEADS + h) * SEQ) * DHEAD;
    const float* Kbase = g_qkv + ((((size_t)1 * BATCH + b) * HEADS + h) * SEQ) * DHEAD;
    const float* Vbase = g_qkv + ((((size_t)2 * BATCH + b) * HEADS + h) * SEQ) * DHEAD;

    // Load Q tile: 64x64 floats = 1024 float4, 4 per thread
    #pragma unroll
    for (int i = 0; i < 4; i++) {
        int f  = tid + i * 256;
        int qr = f >> 4;
        int qc = (f & 15) * 4;
        float4 v = *(const float4*)(Qbase + (size_t)(qb * 64 + qr) * DHEAD + qc);
        Qs[qr][qc + 0] = v.x;
        Qs[qr][qc + 1] = v.y;
        Qs[qr][qc + 2] = v.z;
        Qs[qr][qc + 3] = v.w;
    }

    float m = -1e30f, l = 0.f;
    float o[16];
    #pragma unroll
    for (int i = 0; i < 16; i++) o[i] = 0.f;

    const int j0 = cg * 8;
    const int ntiles = 2 * (qb + 1);

    for (int kt = 0; kt < ntiles; kt++) {
        __syncthreads();   // previous AV done (and Q tile ready on first iter)
        // Load K,V tile: 32x64 each = 512 float4 each, 2 per thread
        #pragma unroll
        for (int i = 0; i < 2; i++) {
            int f  = tid + i * 256;
            int kr = f >> 4;
            int kc = (f & 15) * 4;
            float4 kv = *(const float4*)(Kbase + (size_t)(kt * 32 + kr) * DHEAD + kc);
            Ks[kr][kc + 0] = kv.x;
            Ks[kr][kc + 1] = kv.y;
            Ks[kr][kc + 2] = kv.z;
            Ks[kr][kc + 3] = kv.w;
            *(float4*)(&Vs[kr][kc]) =
                *(const float4*)(Vbase + (size_t)(kt * 32 + kr) * DHEAD + kc);
        }
        __syncthreads();

        // S = Q K^T for this thread's 8 columns
        float s[8];
        #pragma unroll
        for (int j = 0; j < 8; j++) s[j] = 0.f;
        #pragma unroll 8
        for (int d = 0; d < 64; d++) {
            float q = Qs[r][d];
            #pragma unroll
            for (int j = 0; j < 8; j++) s[j] += q * Ks[j0 + j][d];
        }

        // scale + causal mask + row max (over 4-thread group)
        float mt = -1e30f;
        #pragma unroll
        for (int j = 0; j < 8; j++) {
            int kj = kt * 32 + j0 + j;
            s[j] = (kj <= qi) ? s[j] * SCALE : -1e30f;
            mt = fmaxf(mt, s[j]);
        }
        mt = fmaxf(mt, __shfl_xor_sync(0xffffffffu, mt, 1));
        mt = fmaxf(mt, __shfl_xor_sync(0xffffffffu, mt, 2));

        float mnew = fmaxf(m, mt);
        float corr = __expf(m - mnew);
        float psum = 0.f;
        #pragma unroll
        for (int j = 0; j < 8; j++) {
            float p = __expf(s[j] - mnew);
            Ss[r][j0 + j] = p;
            psum += p;
        }
        psum += __shfl_xor_sync(0xffffffffu, psum, 1);
        psum += __shfl_xor_sync(0xffffffffu, psum, 2);
        l = l * corr + psum;
        m = mnew;
        #pragma unroll
        for (int i = 0; i < 16; i++) o[i] *= corr;

        __syncwarp();   // P row written by same-warp 4-group

        // O += P V   (thread owns d = cg + 4*dd, dd=0..15)
        #pragma unroll 4
        for (int j = 0; j < 32; j++) {
            float p = Ss[r][j];
            #pragma unroll
            for (int dd = 0; dd < 16; dd++)
                o[dd] += p * Vs[j][cg + 4 * dd];
        }
    }

    // Normalize + write to g_attn[b][n][h*64 + d]
    float inv = 1.f / l;
    float* dst = g_attn + ((size_t)b * SEQ + qi) * INNER + h * DHEAD;
    #pragma unroll
    for (int dd = 0; dd < 16; dd++)
        dst[cg + 4 * dd] = o[dd] * inv;
}

// ---------------------------------------------------------------------------
extern "C" void kernel_launch(void* const* d_in, const int* in_sizes, int n_in,
                              void* d_out, int out_size)
{
    const float* x     = (const float*)d_in[0];
    const float* w_qkv = (const float*)d_in[1];
    const float* w_out = (const float*)d_in[2];
    const float* b_out = (const float*)d_in[3];
    float* out = (float*)d_out;

    dim3 blk(256);

    // 1) QKV projection: [8192,1024] x [1024,3072] -> scatter into g_qkv
    gemm_kernel<0><<<dim3((3*INNER)/BN, M_ROWS/BM), blk>>>(x, w_qkv, nullptr, nullptr,
                                                           M_ROWS, 3*INNER, DIM);

    // 2) Causal attention -> g_attn
    attn_kernel<<<dim3(SEQ/64, BATCH*HEADS), blk>>>();

    // 3) Output projection + bias: [8192,1024] x [1024,1024] -> d_out
    gemm_kernel<1><<<dim3(DIM/BN, M_ROWS/BM), blk>>>(nullptr, w_out, b_out, out,
                                                     M_ROWS, DIM, DIM);
}

// round 5
// speedup vs baseline: 1.4134x; 1.4134x over previous
#include <cuda_runtime.h>
#include <cstdint>
#include <cstddef>

// Problem constants
#define BATCH 4
#define SEQ   2048
#define DIM   1024
#define HEADS 16
#define DHEAD 64
#define INNER (HEADS*DHEAD)      // 1024
#define M_ROWS (BATCH*SEQ)       // 8192
#define SCALE 0.125f             // 64^-0.5

// Scratch (no allocations allowed -> __device__ globals)
__device__ float g_qkv[(size_t)3*BATCH*HEADS*SEQ*DHEAD];                 // [which][b][h][n][d]
__device__ float g_attn[(size_t)BATCH*SEQ*INNER];                        // [b][n][h*64+d], tf32-rounded
__device__ float g_wt[(size_t)(3*INNER)*DIM + (size_t)DIM*INNER];        // Wt_qkv[3072][1024] ++ Wt_out[1024][1024], tf32-rounded
__device__ float g_xr[(size_t)M_ROWS*DIM];                               // x rounded to tf32

// ---------------------------------------------------------------------------
// Helpers
// ---------------------------------------------------------------------------
__device__ __forceinline__ float tf32_rn(float x) {
    uint32_t u;
    asm("cvt.rn.tf32.f32 %0, %1;" : "=r"(u) : "f"(x));
    return __uint_as_float(u);
}
__device__ __forceinline__ uint32_t smem_u32(const void* p) {
    uint32_t a;
    asm("{ .reg .u64 t; cvta.to.shared.u64 t, %1; cvt.u32.u64 %0, t; }" : "=r"(a) : "l"(p));
    return a;
}
__device__ __forceinline__ void cp_async16(uint32_t dst, const void* src) {
    asm volatile("cp.async.ca.shared.global [%0], [%1], 16;" :: "r"(dst), "l"(src));
}
#define CP_COMMIT() asm volatile("cp.async.commit_group;" ::: "memory")
#define CP_WAIT(n)  asm volatile("cp.async.wait_group %0;" :: "n"(n) : "memory")

__device__ __forceinline__ void mma_tf32(float* d, const uint32_t* a, const uint32_t* b) {
    asm volatile(
        "mma.sync.aligned.m16n8k8.row.col.f32.tf32.tf32.f32 "
        "{%0,%1,%2,%3}, {%4,%5,%6,%7}, {%8,%9}, {%0,%1,%2,%3};"
        : "+f"(d[0]), "+f"(d[1]), "+f"(d[2]), "+f"(d[3])
        : "r"(a[0]), "r"(a[1]), "r"(a[2]), "r"(a[3]), "r"(b[0]), "r"(b[1]));
}

// ---------------------------------------------------------------------------
// Pre-round x to tf32 (float4 grid-stride)
// ---------------------------------------------------------------------------
__global__ __launch_bounds__(256) void round_x(const float* __restrict__ src, float* __restrict__ dst, int n4)
{
    int i = blockIdx.x * blockDim.x + threadIdx.x;
    if (i < n4) {
        float4 v = ((const float4*)src)[i];
        v.x = tf32_rn(v.x); v.y = tf32_rn(v.y); v.z = tf32_rn(v.z); v.w = tf32_rn(v.w);
        ((float4*)dst)[i] = v;
    }
}

// ---------------------------------------------------------------------------
// Weight transpose + tf32-RN: g_wt[dstOff + c*R + r] = rn(src[r*C + c])
// ---------------------------------------------------------------------------
__global__ __launch_bounds__(256) void transpose_rn(const float* __restrict__ src,
                                                    int R, int C, size_t dstOff)
{
    __shared__ float t[32][33];
    const int bx = blockIdx.x * 32;   // over C
    const int by = blockIdx.y * 32;   // over R
    const int tx = threadIdx.x, ty = threadIdx.y;   // (32, 8)
    #pragma unroll
    for (int i = 0; i < 32; i += 8)
        t[ty + i][tx] = tf32_rn(src[(size_t)(by + ty + i) * C + bx + tx]);
    __syncthreads();
    float* dst = g_wt + dstOff;
    #pragma unroll
    for (int i = 0; i < 32; i += 8)
        dst[(size_t)(bx + ty + i) * R + by + tx] = t[tx][ty + i];
}

// ---------------------------------------------------------------------------
// mma.sync tf32 GEMM: C[M,N] = A[M,K] @ Bt[N,K]^T
//   MODE 0: A = g_xr, scatter epilogue into g_qkv        (N=3072)
//   MODE 1: A = g_attn, epilogue writes Cout + bias      (N=1024)
// Block tile 128x128x32, 256 threads (8 warps, 2x4), warp tile 64x32.
// cp.async double-buffered SMEM; xor-swizzled tiles -> conflict-free frags.
// ---------------------------------------------------------------------------
#define TILE_BYTES 16384              // 128 rows * 32 floats * 4B
#define STAGE_BYTES (2*TILE_BYTES)    // A + B
#define GSMEM_TOTAL (2*STAGE_BYTES)   // 2 stages = 64 KB

template<int MODE>
__global__ __launch_bounds__(256) void gemm_mma(const float* __restrict__ bias,
                                                float* __restrict__ Cout,
                                                int N, int K, size_t wtOff)
{
    extern __shared__ char smem[];
    const uint32_t sb = smem_u32(smem);

    const int tid  = threadIdx.x;
    const int wid  = tid >> 5;
    const int lane = tid & 31;
    const int g    = lane >> 2;       // 0..7
    const int tg   = lane & 3;        // 0..3
    const int wm   = wid >> 2;        // 0..1 : 64-row slab
    const int wn   = wid & 3;         // 0..3 : 32-col slab
    const int rowBase = blockIdx.y * 128;
    const int colBase = blockIdx.x * 128;

    const float* A  = (MODE == 0) ? g_xr : g_attn;
    const float* Bt = g_wt + wtOff;
    const float* Abase = A  + (size_t)rowBase * K;
    const float* Bbase = Bt + (size_t)colBase * K;

    // cp.async addressing (per thread, 4 x 16B per tile)
    const int ldRow = tid >> 3;              // base row, +32 each iter... (f>>3 with f=tid+i*256)
    const int ldC4  = tid & 7;               // float4 column

    float acc[4][4][4];
    #pragma unroll
    for (int mt = 0; mt < 4; mt++)
        #pragma unroll
        for (int nt = 0; nt < 4; nt++)
            #pragma unroll
            for (int e = 0; e < 4; e++) acc[mt][nt][e] = 0.f;

    const int NCH = K / 32;

    // Issue loads for chunk c into stage (c&1)
    auto issue = [&](int c) {
        const int s = c & 1;
        const uint32_t aB = sb + s * STAGE_BYTES;
        const uint32_t bB = aB + TILE_BYTES;
        const float* Ap = Abase + c * 32;
        const float* Bp = Bbase + c * 32;
        #pragma unroll
        for (int i = 0; i < 4; i++) {
            int row = ldRow + i * 32;
            uint32_t off = (uint32_t)row * 128 + ((uint32_t)(ldC4 ^ (row & 7)) << 4);
            cp_async16(aB + off, Ap + (size_t)row * K + ldC4 * 4);
            cp_async16(bB + off, Bp + (size_t)row * K + ldC4 * 4);
        }
        CP_COMMIT();
    };

    issue(0);

    for (int c = 0; c < NCH; c++) {
        if (c + 1 < NCH) { issue(c + 1); CP_WAIT(1); }
        else             { CP_WAIT(0); }
        __syncthreads();

        const int s = c & 1;
        const float* As = (const float*)(smem + s * STAGE_BYTES);
        const float* Bs = As + TILE_BYTES / 4;

        #pragma unroll
        for (int ks = 0; ks < 4; ks++) {
            const int k0  = ks * 8 + tg;
            const int sw0 = k0 ^ (g << 2);
            const int sw1 = (k0 + 4) ^ (g << 2);

            uint32_t af[4][4];
            #pragma unroll
            for (int mt = 0; mt < 4; mt++) {
                int m0 = wm * 64 + mt * 16 + g;
                af[mt][0] = __float_as_uint(As[m0 * 32 + sw0]);
                af[mt][1] = __float_as_uint(As[(m0 + 8) * 32 + sw0]);
                af[mt][2] = __float_as_uint(As[m0 * 32 + sw1]);
                af[mt][3] = __float_as_uint(As[(m0 + 8) * 32 + sw1]);
            }
            uint32_t bf[4][2];
            #pragma unroll
            for (int nt = 0; nt < 4; nt++) {
                int n0 = wn * 32 + nt * 8 + g;
                bf[nt][0] = __float_as_uint(Bs[n0 * 32 + sw0]);
                bf[nt][1] = __float_as_uint(Bs[n0 * 32 + sw1]);
            }
            #pragma unroll
            for (int mt = 0; mt < 4; mt++)
                #pragma unroll
                for (int nt = 0; nt < 4; nt++)
                    mma_tf32(acc[mt][nt], af[mt], bf[nt]);
        }
        __syncthreads();
    }

    // Epilogue: per mma tile, thread owns (g,row) x (tg*2, tg*2+1) pairs
    #pragma unroll
    for (int mt = 0; mt < 4; mt++) {
        #pragma unroll
        for (int nt = 0; nt < 4; nt++) {
            const int c = colBase + wn * 32 + nt * 8 + tg * 2;
            #pragma unroll
            for (int half = 0; half < 2; half++) {
                const int r = rowBase + wm * 64 + mt * 16 + g + half * 8;
                float d0 = acc[mt][nt][half * 2 + 0];
                float d1 = acc[mt][nt][half * 2 + 1];
                if (MODE == 0) {
                    int b   = r >> 11;
                    int n   = r & 2047;
                    int wch = c >> 10;
                    int rem = c & 1023;
                    int h   = rem >> 6;
                    int dlo = rem & 63;
                    float* dst = g_qkv + ((((size_t)wch * BATCH + b) * HEADS + h) * SEQ + n) * DHEAD + dlo;
                    *(float2*)dst = make_float2(d0, d1);
                } else {
                    float* dst = Cout + (size_t)r * N + c;
                    *(float2*)dst = make_float2(d0 + bias[c], d1 + bias[c + 1]);
                }
            }
        }
    }
}

// ---------------------------------------------------------------------------
// Causal flash attention (fp32). Grid: (32 qblocks, 64 bh). Block: 256.
// Output written tf32-rounded so the out-proj GEMM can consume it directly.
// ---------------------------------------------------------------------------
__global__ __launch_bounds__(256) void attn_kernel()
{
    __shared__ float Qs[64][65];
    __shared__ float Ks[32][65];
    __shared__ float Vs[32][64];
    __shared__ float Ss[64][33];

    const int qb  = gridDim.x - 1 - blockIdx.x;
    const int bh  = blockIdx.y;
    const int b   = bh >> 4;
    const int h   = bh & 15;
    const int tid = threadIdx.x;
    const int r   = tid >> 2;
    const int cg  = tid & 3;
    const int qi  = qb * 64 + r;

    const float* Qbase = g_qkv + ((((size_t)0 * BATCH + b) * HEADS + h) * SEQ) * DHEAD;
    const float* Kbase = g_qkv + ((((size_t)1 * BATCH + b) * HEADS + h) * SEQ) * DHEAD;
    const float* Vbase = g_qkv + ((((size_t)2 * BATCH + b) * HEADS + h) * SEQ) * DHEAD;

    #pragma unroll
    for (int i = 0; i < 4; i++) {
        int f  = tid + i * 256;
        int qr = f >> 4;
        int qc = (f & 15) * 4;
        float4 v = *(const float4*)(Qbase + (size_t)(qb * 64 + qr) * DHEAD + qc);
        Qs[qr][qc + 0] = v.x;
        Qs[qr][qc + 1] = v.y;
        Qs[qr][qc + 2] = v.z;
        Qs[qr][qc + 3] = v.w;
    }

    float m = -1e30f, l = 0.f;
    float o[16];
    #pragma unroll
    for (int i = 0; i < 16; i++) o[i] = 0.f;

    const int j0 = cg * 8;
    const int ntiles = 2 * (qb + 1);

    for (int kt = 0; kt < ntiles; kt++) {
        __syncthreads();
        #pragma unroll
        for (int i = 0; i < 2; i++) {
            int f  = tid + i * 256;
            int kr = f >> 4;
            int kc = (f & 15) * 4;
            float4 kv = *(const float4*)(Kbase + (size_t)(kt * 32 + kr) * DHEAD + kc);
            Ks[kr][kc + 0] = kv.x;
            Ks[kr][kc + 1] = kv.y;
            Ks[kr][kc + 2] = kv.z;
            Ks[kr][kc + 3] = kv.w;
            *(float4*)(&Vs[kr][kc]) =
                *(const float4*)(Vbase + (size_t)(kt * 32 + kr) * DHEAD + kc);
        }
        __syncthreads();

        float s[8];
        #pragma unroll
        for (int j = 0; j < 8; j++) s[j] = 0.f;
        #pragma unroll 8
        for (int d = 0; d < 64; d++) {
            float q = Qs[r][d];
            #pragma unroll
            for (int j = 0; j < 8; j++) s[j] += q * Ks[j0 + j][d];
        }

        float mt = -1e30f;
        #pragma unroll
        for (int j = 0; j < 8; j++) {
            int kj = kt * 32 + j0 + j;
            s[j] = (kj <= qi) ? s[j] * SCALE : -1e30f;
            mt = fmaxf(mt, s[j]);
        }
        mt = fmaxf(mt, __shfl_xor_sync(0xffffffffu, mt, 1));
        mt = fmaxf(mt, __shfl_xor_sync(0xffffffffu, mt, 2));

        float mnew = fmaxf(m, mt);
        float corr = __expf(m - mnew);
        float psum = 0.f;
        #pragma unroll
        for (int j = 0; j < 8; j++) {
            float p = __expf(s[j] - mnew);
            Ss[r][j0 + j] = p;
            psum += p;
        }
        psum += __shfl_xor_sync(0xffffffffu, psum, 1);
        psum += __shfl_xor_sync(0xffffffffu, psum, 2);
        l = l * corr + psum;
        m = mnew;
        #pragma unroll
        for (int i = 0; i < 16; i++) o[i] *= corr;

        __syncwarp();

        #pragma unroll 4
        for (int j = 0; j < 32; j++) {
            float p = Ss[r][j];
            #pragma unroll
            for (int dd = 0; dd < 16; dd++)
                o[dd] += p * Vs[j][cg + 4 * dd];
        }
    }

    float inv = 1.f / l;
    float* dst = g_attn + ((size_t)b * SEQ + qi) * INNER + h * DHEAD;
    #pragma unroll
    for (int dd = 0; dd < 16; dd++)
        dst[cg + 4 * dd] = tf32_rn(o[dd] * inv);
}

// ---------------------------------------------------------------------------
extern "C" void kernel_launch(void* const* d_in, const int* in_sizes, int n_in,
                              void* d_out, int out_size)
{
    const float* x     = (const float*)d_in[0];
    const float* w_qkv = (const float*)d_in[1];
    const float* w_out = (const float*)d_in[2];
    const float* b_out = (const float*)d_in[3];
    float* out = (float*)d_out;

    static int smem_set = 0;
    if (!smem_set) {
        cudaFuncSetAttribute(gemm_mma<0>, cudaFuncAttributeMaxDynamicSharedMemorySize, GSMEM_TOTAL);
        cudaFuncSetAttribute(gemm_mma<1>, cudaFuncAttributeMaxDynamicSharedMemorySize, GSMEM_TOTAL);
        smem_set = 1;
    }

    // 0) Pre-round x; transpose + round weights
    {
        int n4 = (M_ROWS * DIM) / 4;
        float* xr;
        cudaGetSymbolAddress((void**)&xr, g_xr);
        round_x<<<(n4 + 255) / 256, 256>>>(x, xr, n4);
    }
    transpose_rn<<<dim3((3*INNER)/32, DIM/32), dim3(32, 8)>>>(w_qkv, DIM, 3*INNER, 0);
    transpose_rn<<<dim3(DIM/32, DIM/32), dim3(32, 8)>>>(w_out, DIM, DIM, (size_t)(3*INNER)*DIM);

    // 1) QKV projection (mma.sync tf32): [8192,1024] x [1024,3072] -> g_qkv scatter
    gemm_mma<0><<<dim3((3*INNER)/128, M_ROWS/128), 256, GSMEM_TOTAL>>>(nullptr, nullptr,
                                                                       3*INNER, DIM, 0);

    // 2) Causal attention -> g_attn (tf32-rounded)
    attn_kernel<<<dim3(SEQ/64, BATCH*HEADS), 256>>>();

    // 3) Output projection + bias (mma.sync tf32): [8192,1024] x [1024,1024] -> d_out
    gemm_mma<1><<<dim3(DIM/128, M_ROWS/128), 256, GSMEM_TOTAL>>>(b_out, out,
                                                                 DIM, DIM, (size_t)(3*INNER)*DIM);
}

// round 9
// speedup vs baseline: 4.7666x; 3.3725x over previous
#include <cuda_runtime.h>
#include <cstdint>
#include <cstddef>

// Problem constants
#define BATCH 4
#define SEQ   2048
#define DIM   1024
#define HEADS 16
#define DHEAD 64
#define INNER (HEADS*DHEAD)      // 1024
#define M_ROWS (BATCH*SEQ)       // 8192
#define SCALE 0.125f             // 64^-0.5

// Scratch (no allocations allowed -> __device__ globals)
__device__ float g_qkv[(size_t)3*BATCH*HEADS*SEQ*DHEAD];                 // [which][b][h][n][d], tf32-rounded
__device__ float g_attn[(size_t)BATCH*SEQ*INNER];                        // [b][n][h*64+d], tf32-rounded
__device__ float g_wt[(size_t)(3*INNER)*DIM + (size_t)DIM*INNER];        // Wt_qkv[3072][1024] ++ Wt_out[1024][1024]
__device__ float g_xr[(size_t)M_ROWS*DIM];                               // x rounded to tf32

// ---------------------------------------------------------------------------
// Helpers
// ---------------------------------------------------------------------------
__device__ __forceinline__ float tf32_rn(float x) {
    uint32_t u;
    asm("cvt.rn.tf32.f32 %0, %1;" : "=r"(u) : "f"(x));
    return __uint_as_float(u);
}
__device__ __forceinline__ uint32_t smem_u32(const void* p) {
    uint32_t a;
    asm("{ .reg .u64 t; cvta.to.shared.u64 t, %1; cvt.u32.u64 %0, t; }" : "=r"(a) : "l"(p));
    return a;
}
__device__ __forceinline__ void cp_async16(uint32_t dst, const void* src) {
    asm volatile("cp.async.ca.shared.global [%0], [%1], 16;" :: "r"(dst), "l"(src));
}
#define CP_COMMIT() asm volatile("cp.async.commit_group;" ::: "memory")
#define CP_WAIT(n)  asm volatile("cp.async.wait_group %0;" :: "n"(n) : "memory")

__device__ __forceinline__ void mma_tf32(float* d, const uint32_t* a, const uint32_t* b) {
    asm volatile(
        "mma.sync.aligned.m16n8k8.row.col.f32.tf32.tf32.f32 "
        "{%0,%1,%2,%3}, {%4,%5,%6,%7}, {%8,%9}, {%0,%1,%2,%3};"
        : "+f"(d[0]), "+f"(d[1]), "+f"(d[2]), "+f"(d[3])
        : "r"(a[0]), "r"(a[1]), "r"(a[2]), "r"(a[3]), "r"(b[0]), "r"(b[1]));
}

// ---------------------------------------------------------------------------
// Pre-round x to tf32 (float4 grid-stride)
// ---------------------------------------------------------------------------
__global__ __launch_bounds__(256) void round_x(const float* __restrict__ src, float* __restrict__ dst, int n4)
{
    int i = blockIdx.x * blockDim.x + threadIdx.x;
    if (i < n4) {
        float4 v = ((const float4*)src)[i];
        v.x = tf32_rn(v.x); v.y = tf32_rn(v.y); v.z = tf32_rn(v.z); v.w = tf32_rn(v.w);
        ((float4*)dst)[i] = v;
    }
}

// ---------------------------------------------------------------------------
// Weight transpose + tf32-RN: g_wt[dstOff + c*R + r] = rn(src[r*C + c])
// ---------------------------------------------------------------------------
__global__ __launch_bounds__(256) void transpose_rn(const float* __restrict__ src,
                                                    int R, int C, size_t dstOff)
{
    __shared__ float t[32][33];
    const int bx = blockIdx.x * 32;   // over C
    const int by = blockIdx.y * 32;   // over R
    const int tx = threadIdx.x, ty = threadIdx.y;   // (32, 8)
    #pragma unroll
    for (int i = 0; i < 32; i += 8)
        t[ty + i][tx] = tf32_rn(src[(size_t)(by + ty + i) * C + bx + tx]);
    __syncthreads();
    float* dst = g_wt + dstOff;
    #pragma unroll
    for (int i = 0; i < 32; i += 8)
        dst[(size_t)(bx + ty + i) * R + by + tx] = t[tx][ty + i];
}

// ---------------------------------------------------------------------------
// mma.sync tf32 GEMM: C[M,N] = A[M,K] @ Bt[N,K]^T
//   MODE 0: A = g_xr, scatter epilogue into g_qkv (tf32-rounded)  (N=3072)
//   MODE 1: A = g_attn, epilogue writes Cout + bias               (N=1024)
// ---------------------------------------------------------------------------
#define TILE_BYTES 16384              // 128 rows * 32 floats * 4B
#define STAGE_BYTES (2*TILE_BYTES)    // A + B
#define GSMEM_TOTAL (2*STAGE_BYTES)   // 2 stages = 64 KB

template<int MODE>
__global__ __launch_bounds__(256) void gemm_mma(const float* __restrict__ bias,
                                                float* __restrict__ Cout,
                                                int N, int K, size_t wtOff)
{
    extern __shared__ char smem[];
    const uint32_t sb = smem_u32(smem);

    const int tid  = threadIdx.x;
    const int wid  = tid >> 5;
    const int lane = tid & 31;
    const int g    = lane >> 2;
    const int tg   = lane & 3;
    const int wm   = wid >> 2;
    const int wn   = wid & 3;
    const int rowBase = blockIdx.y * 128;
    const int colBase = blockIdx.x * 128;

    const float* A  = (MODE == 0) ? g_xr : g_attn;
    const float* Bt = g_wt + wtOff;
    const float* Abase = A  + (size_t)rowBase * K;
    const float* Bbase = Bt + (size_t)colBase * K;

    const int ldRow = tid >> 3;
    const int ldC4  = tid & 7;

    float acc[4][4][4];
    #pragma unroll
    for (int mt = 0; mt < 4; mt++)
        #pragma unroll
        for (int nt = 0; nt < 4; nt++)
            #pragma unroll
            for (int e = 0; e < 4; e++) acc[mt][nt][e] = 0.f;

    const int NCH = K / 32;

    auto issue = [&](int c) {
        const int s = c & 1;
        const uint32_t aB = sb + s * STAGE_BYTES;
        const uint32_t bB = aB + TILE_BYTES;
        const float* Ap = Abase + c * 32;
        const float* Bp = Bbase + c * 32;
        #pragma unroll
        for (int i = 0; i < 4; i++) {
            int row = ldRow + i * 32;
            uint32_t off = (uint32_t)row * 128 + ((uint32_t)(ldC4 ^ (row & 7)) << 4);
            cp_async16(aB + off, Ap + (size_t)row * K + ldC4 * 4);
            cp_async16(bB + off, Bp + (size_t)row * K + ldC4 * 4);
        }
        CP_COMMIT();
    };

    issue(0);

    for (int c = 0; c < NCH; c++) {
        if (c + 1 < NCH) { issue(c + 1); CP_WAIT(1); }
        else             { CP_WAIT(0); }
        __syncthreads();

        const int s = c & 1;
        const float* As = (const float*)(smem + s * STAGE_BYTES);
        const float* Bs = As + TILE_BYTES / 4;

        #pragma unroll
        for (int ks = 0; ks < 4; ks++) {
            const int k0  = ks * 8 + tg;
            const int sw0 = k0 ^ (g << 2);
            const int sw1 = (k0 + 4) ^ (g << 2);

            uint32_t af[4][4];
            #pragma unroll
            for (int mt = 0; mt < 4; mt++) {
                int m0 = wm * 64 + mt * 16 + g;
                af[mt][0] = __float_as_uint(As[m0 * 32 + sw0]);
                af[mt][1] = __float_as_uint(As[(m0 + 8) * 32 + sw0]);
                af[mt][2] = __float_as_uint(As[m0 * 32 + sw1]);
                af[mt][3] = __float_as_uint(As[(m0 + 8) * 32 + sw1]);
            }
            uint32_t bf[4][2];
            #pragma unroll
            for (int nt = 0; nt < 4; nt++) {
                int n0 = wn * 32 + nt * 8 + g;
                bf[nt][0] = __float_as_uint(Bs[n0 * 32 + sw0]);
                bf[nt][1] = __float_as_uint(Bs[n0 * 32 + sw1]);
            }
            #pragma unroll
            for (int mt = 0; mt < 4; mt++)
                #pragma unroll
                for (int nt = 0; nt < 4; nt++)
                    mma_tf32(acc[mt][nt], af[mt], bf[nt]);
        }
        __syncthreads();
    }

    #pragma unroll
    for (int mt = 0; mt < 4; mt++) {
        #pragma unroll
        for (int nt = 0; nt < 4; nt++) {
            const int c = colBase + wn * 32 + nt * 8 + tg * 2;
            #pragma unroll
            for (int half = 0; half < 2; half++) {
                const int r = rowBase + wm * 64 + mt * 16 + g + half * 8;
                float d0 = acc[mt][nt][half * 2 + 0];
                float d1 = acc[mt][nt][half * 2 + 1];
                if (MODE == 0) {
                    int b   = r >> 11;
                    int n   = r & 2047;
                    int wch = c >> 10;
                    int rem = c & 1023;
                    int h   = rem >> 6;
                    int dlo = rem & 63;
                    float* dst = g_qkv + ((((size_t)wch * BATCH + b) * HEADS + h) * SEQ + n) * DHEAD + dlo;
                    *(float2*)dst = make_float2(tf32_rn(d0), tf32_rn(d1));
                } else {
                    float* dst = Cout + (size_t)r * N + c;
                    *(float2*)dst = make_float2(d0 + bias[c], d1 + bias[c + 1]);
                }
            }
        }
    }
}

// ---------------------------------------------------------------------------
// Causal flash attention, mma.sync tf32.
// Grid: (16 qblocks, 64 bh), 256 threads (8 warps x 16 query rows).
// Block tile: 128 queries x 128-key tiles. S in registers; P via warp-private
// SMEM slab; V staged transposed for the PV B operand.
// ---------------------------------------------------------------------------
#define KSP 68     // Ks row stride (floats): 64 + 4 pad
#define VSP 132    // Vt row stride: 128 + 4 pad
#define PSP 132    // Ps row stride: 128 + 4 pad
#define ATT_SMEM_FLOATS (128*KSP + 64*VSP + 8*16*PSP)
#define ATT_SMEM_BYTES  (ATT_SMEM_FLOATS*4)   // 136192

__global__ __launch_bounds__(256, 1) void attn_mma()
{
    extern __shared__ float sm[];
    float* Ks = sm;                         // [128][KSP]  K tile, [key][d]
    float* Vt = sm + 128*KSP;               // [64][VSP]   V transposed, [d][key]
    float* Ps = Vt + 64*VSP;                // [8][16][PSP] per-warp P slab

    const int tid  = threadIdx.x;
    const int wid  = tid >> 5;
    const int lane = tid & 31;
    const int g    = lane >> 2;
    const int tg   = lane & 3;

    const int qb = gridDim.x - 1 - blockIdx.x;   // big-work blocks first
    const int bh = blockIdx.y;
    const int b  = bh >> 4;
    const int h  = bh & 15;
    const int rowA = qb * 128 + wid * 16;        // warp's query-row base
    const int qi0 = rowA + g;
    const int qi1 = rowA + g + 8;

    const float* Qb = g_qkv + (((size_t)0 * BATCH + b) * HEADS + h) * SEQ * DHEAD;
    const float* Kb = g_qkv + (((size_t)1 * BATCH + b) * HEADS + h) * SEQ * DHEAD;
    const float* Vb = g_qkv + (((size_t)2 * BATCH + b) * HEADS + h) * SEQ * DHEAD;

    // Q fragments in registers (data already tf32-rounded by GEMM epilogue)
    uint32_t qf[8][4];
    #pragma unroll
    for (int ks = 0; ks < 8; ks++) {
        const float* Qr0 = Qb + (size_t)qi0 * DHEAD + ks * 8;
        const float* Qr1 = Qb + (size_t)qi1 * DHEAD + ks * 8;
        qf[ks][0] = __float_as_uint(Qr0[tg]);
        qf[ks][1] = __float_as_uint(Qr1[tg]);
        qf[ks][2] = __float_as_uint(Qr0[tg + 4]);
        qf[ks][3] = __float_as_uint(Qr1[tg + 4]);
    }

    float o[8][4];
    #pragma unroll
    for (int dt = 0; dt < 8; dt++)
        #pragma unroll
        for (int e = 0; e < 4; e++) o[dt][e] = 0.f;
    float m0 = -1e30f, m1 = -1e30f, l0 = 0.f, l1 = 0.f;

    float* Pw = Ps + wid * 16 * PSP;

    for (int kt = 0; kt <= qb; kt++) {
        __syncthreads();
        // K tile via cp.async: 128 rows x 64 floats = 2048 float4 (8 per thread)
        {
            const float* Kp = Kb + (size_t)kt * 128 * DHEAD;
            #pragma unroll
            for (int i = 0; i < 8; i++) {
                int f = tid + i * 256;          // 0..2047
                int r = f >> 4, c4 = f & 15;    // r: 0..127, c4: 0..15
                cp_async16(smem_u32(Ks + r * KSP + c4 * 4), Kp + (size_t)r * 64 + c4 * 4);
            }
            CP_COMMIT();
        }
        // V tile transposed: Vt[d][j]
        {
            const float* Vp = Vb + (size_t)kt * 128 * DHEAD;
            #pragma unroll
            for (int i = 0; i < 8; i++) {
                int f = tid + i * 256;          // 0..2047
                int j = f & 127, c4 = f >> 7;   // c4: 0..15
                float4 v = *(const float4*)(Vp + (size_t)j * 64 + c4 * 4);
                Vt[(c4 * 4 + 0) * VSP + j] = v.x;
                Vt[(c4 * 4 + 1) * VSP + j] = v.y;
                Vt[(c4 * 4 + 2) * VSP + j] = v.z;
                Vt[(c4 * 4 + 3) * VSP + j] = v.w;
            }
        }
        CP_WAIT(0);
        __syncthreads();

        // S = Q K^T  (16 n-tiles of 8 keys)
        float sacc[16][4];
        #pragma unroll
        for (int nt = 0; nt < 16; nt++)
            #pragma unroll
            for (int e = 0; e < 4; e++) sacc[nt][e] = 0.f;
        #pragma unroll
        for (int ks = 0; ks < 8; ks++) {
            #pragma unroll
            for (int nt = 0; nt < 16; nt++) {
                uint32_t bf[2];
                const float* kr = Ks + (nt * 8 + g) * KSP + ks * 8;
                bf[0] = __float_as_uint(kr[tg]);
                bf[1] = __float_as_uint(kr[tg + 4]);
                mma_tf32(sacc[nt], qf[ks], bf);
            }
        }

        // Causal mask (diagonal tile only)
        const int jb = kt * 128;
        if (kt == qb) {
            #pragma unroll
            for (int nt = 0; nt < 16; nt++) {
                #pragma unroll
                for (int e = 0; e < 2; e++) {
                    int col = jb + nt * 8 + tg * 2 + e;
                    if (col > qi0) sacc[nt][e]     = -1e30f;
                    if (col > qi1) sacc[nt][2 + e] = -1e30f;
                }
            }
        }

        // Online softmax (rows qi0 / qi1)
        float mt0 = -1e30f, mt1 = -1e30f;
        #pragma unroll
        for (int nt = 0; nt < 16; nt++) {
            mt0 = fmaxf(mt0, fmaxf(sacc[nt][0], sacc[nt][1]));
            mt1 = fmaxf(mt1, fmaxf(sacc[nt][2], sacc[nt][3]));
        }
        mt0 = fmaxf(mt0, __shfl_xor_sync(0xffffffffu, mt0, 1));
        mt0 = fmaxf(mt0, __shfl_xor_sync(0xffffffffu, mt0, 2));
        mt1 = fmaxf(mt1, __shfl_xor_sync(0xffffffffu, mt1, 1));
        mt1 = fmaxf(mt1, __shfl_xor_sync(0xffffffffu, mt1, 2));

        float mn0 = fmaxf(m0, mt0 * SCALE);
        float mn1 = fmaxf(m1, mt1 * SCALE);
        float corr0 = __expf(m0 - mn0);
        float corr1 = __expf(m1 - mn1);

        float ps0 = 0.f, ps1 = 0.f;
        #pragma unroll
        for (int nt = 0; nt < 16; nt++) {
            float p00 = __expf(sacc[nt][0] * SCALE - mn0);
            float p01 = __expf(sacc[nt][1] * SCALE - mn0);
            float p10 = __expf(sacc[nt][2] * SCALE - mn1);
            float p11 = __expf(sacc[nt][3] * SCALE - mn1);
            ps0 += p00 + p01;
            ps1 += p10 + p11;
            *(float2*)(Pw + g * PSP + nt * 8 + tg * 2)       = make_float2(tf32_rn(p00), tf32_rn(p01));
            *(float2*)(Pw + (g + 8) * PSP + nt * 8 + tg * 2) = make_float2(tf32_rn(p10), tf32_rn(p11));
        }
        ps0 += __shfl_xor_sync(0xffffffffu, ps0, 1);
        ps0 += __shfl_xor_sync(0xffffffffu, ps0, 2);
        ps1 += __shfl_xor_sync(0xffffffffu, ps1, 1);
        ps1 += __shfl_xor_sync(0xffffffffu, ps1, 2);
        l0 = l0 * corr0 + ps0;
        l1 = l1 * corr1 + ps1;
        m0 = mn0; m1 = mn1;
        #pragma unroll
        for (int dt = 0; dt < 8; dt++) {
            o[dt][0] *= corr0; o[dt][1] *= corr0;
            o[dt][2] *= corr1; o[dt][3] *= corr1;
        }

        __syncwarp();

        // O += P V  (16 k-steps over keys, 8 d-tiles)
        #pragma unroll
        for (int jks = 0; jks < 16; jks++) {
            uint32_t af[4];
            const float* p0 = Pw + g * PSP + jks * 8;
            const float* p1 = Pw + (g + 8) * PSP + jks * 8;
            af[0] = __float_as_uint(p0[tg]);
            af[1] = __float_as_uint(p1[tg]);
            af[2] = __float_as_uint(p0[tg + 4]);
            af[3] = __float_as_uint(p1[tg + 4]);
            #pragma unroll
            for (int dt = 0; dt < 8; dt++) {
                uint32_t bf[2];
                const float* vr = Vt + (dt * 8 + g) * VSP + jks * 8;
                bf[0] = __float_as_uint(vr[tg]);
                bf[1] = __float_as_uint(vr[tg + 4]);
                mma_tf32(o[dt], af, bf);
            }
        }
    }

    // Epilogue: normalize, write tf32-rounded to g_attn[b][n][h*64+d]
    float inv0 = 1.f / l0;
    float inv1 = 1.f / l1;
    float* d0 = g_attn + ((size_t)b * SEQ + qi0) * INNER + h * DHEAD;
    float* d1 = g_attn + ((size_t)b * SEQ + qi1) * INNER + h * DHEAD;
    #pragma unroll
    for (int dt = 0; dt < 8; dt++) {
        int c = dt * 8 + tg * 2;
        *(float2*)(d0 + c) = make_float2(tf32_rn(o[dt][0] * inv0), tf32_rn(o[dt][1] * inv0));
        *(float2*)(d1 + c) = make_float2(tf32_rn(o[dt][2] * inv1), tf32_rn(o[dt][3] * inv1));
    }
}

// ---------------------------------------------------------------------------
extern "C" void kernel_launch(void* const* d_in, const int* in_sizes, int n_in,
                              void* d_out, int out_size)
{
    const float* x     = (const float*)d_in[0];
    const float* w_qkv = (const float*)d_in[1];
    const float* w_out = (const float*)d_in[2];
    const float* b_out = (const float*)d_in[3];
    float* out = (float*)d_out;

    static int attr_set = 0;
    if (!attr_set) {
        cudaFuncSetAttribute(gemm_mma<0>, cudaFuncAttributeMaxDynamicSharedMemorySize, GSMEM_TOTAL);
        cudaFuncSetAttribute(gemm_mma<1>, cudaFuncAttributeMaxDynamicSharedMemorySize, GSMEM_TOTAL);
        cudaFuncSetAttribute(attn_mma,    cudaFuncAttributeMaxDynamicSharedMemorySize, ATT_SMEM_BYTES);
        attr_set = 1;
    }

    // 0) Pre-round x; transpose + round weights
    {
        int n4 = (M_ROWS * DIM) / 4;
        float* xr;
        cudaGetSymbolAddress((void**)&xr, g_xr);
        round_x<<<(n4 + 255) / 256, 256>>>(x, xr, n4);
    }
    transpose_rn<<<dim3((3*INNER)/32, DIM/32), dim3(32, 8)>>>(w_qkv, DIM, 3*INNER, 0);
    transpose_rn<<<dim3(DIM/32, DIM/32), dim3(32, 8)>>>(w_out, DIM, DIM, (size_t)(3*INNER)*DIM);

    // 1) QKV projection (mma.sync tf32) -> g_qkv (tf32-rounded)
    gemm_mma<0><<<dim3((3*INNER)/128, M_ROWS/128), 256, GSMEM_TOTAL>>>(nullptr, nullptr,
                                                                       3*INNER, DIM, 0);

    // 2) Causal flash attention (mma.sync tf32) -> g_attn
    attn_mma<<<dim3(SEQ/128, BATCH*HEADS), 256, ATT_SMEM_BYTES>>>();

    // 3) Output projection + bias (mma.sync tf32) -> d_out
    gemm_mma<1><<<dim3(DIM/128, M_ROWS/128), 256, GSMEM_TOTAL>>>(b_out, out,
                                                                 DIM, DIM, (size_t)(3*INNER)*DIM);
}